// round 9
// baseline (speedup 1.0000x reference)
#include <cuda_runtime.h>
#include <math.h>

// Problem constants (fixed shapes from the reference)
#define N_ENT   14541
#define N_REL   237
#define M_EDGES 272115
#define D       256
#define BS      16
#define NT      4                      // entities per warp tile
#define OUT_ELEMS (N_ENT * BS)

#define NBLK    148                    // one block per SM (co-residency guaranteed)
#define THREADS 256
#define GWARPS  (NBLK * THREADS / 32)  // 1184
#define GTHREADS (NBLK * THREADS)      // 37888
#define TILES   ((N_ENT + NT - 1) / NT) // 3636

// Scratch (static device arrays; no runtime allocation)
__device__ float        g_sig[N_ENT * BS];
__device__ int          g_bar_count = 0;
__device__ volatile int g_bar_sense = 0;

// ---------------------------------------------------------------------------
// Single fused kernel:
//   phase 1: dist  — sig[n][b] = sigmoid(12 - sum_d |rel|*|emb - all_emb|),
//            self-masked to 0. Warps loop over NT=4-entity tiles.
//   barrier: sense-reversing grid barrier (148 co-resident blocks).
//   phase 2: edge  — filter edges by relation match, gather sig[head][b],
//            atomic scatter-add onto out[b][tail].
// ---------------------------------------------------------------------------
__global__ void __launch_bounds__(THREADS) fused_kernel(
    const float* __restrict__ emb,
    const float* __restrict__ all_emb,
    const float* __restrict__ tail_r,
    const int*   __restrict__ source_idx,
    const int*   __restrict__ relation_ids,
    const int*   __restrict__ heads,
    const int*   __restrict__ tails,
    const int*   __restrict__ rels,
    float*       __restrict__ out)
{
    __shared__ float    es[BS * D];     // emb[b][d]
    __shared__ float    rs[BS * D];     // |tail_r[relation_ids[b]][d]|
    __shared__ int      s_rel[BS];
    __shared__ int      s_src[BS];
    __shared__ unsigned s_mask[N_REL];  // relation -> batch bitmask

    const int tid  = threadIdx.x;
    const int lane = tid & 31;
    const int gtid = blockIdx.x * THREADS + tid;

    // Zero the output buffer (930 KB over 37888 threads, coalesced).
    for (int i = gtid; i < OUT_ELEMS; i += GTHREADS) out[i] = 0.f;

    if (tid < BS) {
        s_rel[tid] = relation_ids[tid];
        s_src[tid] = source_idx[tid];
    }
    __syncthreads();

    if (tid < N_REL) {
        unsigned m = 0;
        #pragma unroll
        for (int b = 0; b < BS; b++)
            m |= (s_rel[b] == tid) ? (1u << b) : 0u;
        s_mask[tid] = m;
    }
    for (int i = tid; i < BS * D; i += THREADS) {
        int b = i >> 8;          // i / D
        int d = i & (D - 1);     // i % D
        es[i] = emb[i];
        rs[i] = fabsf(tail_r[s_rel[b] * D + d]);
    }
    __syncthreads();

    // ---- Phase 1: distance tiles (R3 formulation, looped over tiles) ----
    const int gwarp = blockIdx.x * (THREADS / 32) + (tid >> 5);
    const float4* es4 = (const float4*)es;
    const float4* rs4 = (const float4*)rs;

    for (int tile = gwarp; tile < TILES; tile += GWARPS) {
        const int n0 = tile * NT;

        // Preload all_emb rows (coalesced LDG.128); clamp only the last tile.
        float4 xl[NT], xh[NT];
        #pragma unroll
        for (int n = 0; n < NT; n++) {
            int nn = n0 + n; if (nn >= N_ENT) nn = N_ENT - 1;
            const float4* row = (const float4*)(all_emb + nn * D);
            xl[n] = row[lane];
            xh[n] = row[32 + lane];
        }

        float acc[NT * BS];
        #pragma unroll
        for (int i = 0; i < NT * BS; i++) acc[i] = 0.f;

        #pragma unroll
        for (int b = 0; b < BS; b++) {
            float4 e0 = es4[b * 64 + lane];
            float4 e1 = es4[b * 64 + 32 + lane];
            float4 r0 = rs4[b * 64 + lane];
            float4 r1 = rs4[b * 64 + 32 + lane];
            #pragma unroll
            for (int n = 0; n < NT; n++) {
                float s = acc[n * BS + b];
                s += r0.x * fabsf(e0.x - xl[n].x);
                s += r0.y * fabsf(e0.y - xl[n].y);
                s += r0.z * fabsf(e0.z - xl[n].z);
                s += r0.w * fabsf(e0.w - xl[n].w);
                s += r1.x * fabsf(e1.x - xh[n].x);
                s += r1.y * fabsf(e1.y - xh[n].y);
                s += r1.z * fabsf(e1.z - xh[n].z);
                s += r1.w * fabsf(e1.w - xh[n].w);
                acc[n * BS + b] = s;
            }
        }

        // Value-splitting butterfly: 64 partials -> 62 shuffles; lane L ends
        // with flat sums 2L and 2L+1, where flat = n_local*16 + b.
        #pragma unroll
        for (int step = 0; step < 5; step++) {
            const int mask = 16 >> step;
            const int V    = 64 >> step;
            const bool hi  = (lane & mask) != 0;
            #pragma unroll
            for (int i = 0; i < V / 2; i++) {
                float send = hi ? acc[i]         : acc[i + V / 2];
                float keep = hi ? acc[i + V / 2] : acc[i];
                float other = __shfl_xor_sync(0xffffffffu, send, mask);
                acc[i] = keep + other;
            }
        }

        const int f  = 2 * lane;
        const int nn = n0 + (f >> 4);
        const int b  = f & 15;
        if (nn < N_ENT) {
            float s0 = 1.0f / (1.0f + __expf(acc[0] - 12.0f));
            float s1 = 1.0f / (1.0f + __expf(acc[1] - 12.0f));
            if (nn == s_src[b])     s0 = 0.0f;
            if (nn == s_src[b + 1]) s1 = 0.0f;
            *(float2*)(g_sig + nn * BS + b) = make_float2(s0, s1);
        }
    }

    // ---- Grid barrier (sense-reversing; replay-safe) ----
    __syncthreads();
    if (tid == 0) {
        const int s = g_bar_sense;
        __threadfence();                       // publish sig + out zeroing
        if (atomicAdd(&g_bar_count, 1) == NBLK - 1) {
            g_bar_count = 0;
            __threadfence();
            g_bar_sense = s ^ 1;               // release
        } else {
            while (g_bar_sense == s) {}
        }
        __threadfence();
    }
    __syncthreads();

    // ---- Phase 2: edge filter + scatter ----
    for (int i = gtid; i < M_EDGES; i += GTHREADS) {
        const int r = __ldg(rels + i);
        unsigned m = s_mask[r];
        if (!m) continue;
        const int h = __ldg(heads + i);
        const int t = __ldg(tails + i);
        do {
            int b = __ffs(m) - 1;
            m &= m - 1;
            atomicAdd(out + b * N_ENT + t, g_sig[h * BS + b]);
        } while (m);
    }
}

// ---------------------------------------------------------------------------
extern "C" void kernel_launch(void* const* d_in, const int* in_sizes, int n_in,
                              void* d_out, int out_size) {
    const float* emb          = (const float*)d_in[0];
    const float* all_emb      = (const float*)d_in[1];
    const float* tail_r       = (const float*)d_in[2];
    const int*   source_idx   = (const int*)  d_in[3];
    const int*   relation_ids = (const int*)  d_in[4];
    const int*   heads        = (const int*)  d_in[5];
    const int*   tails        = (const int*)  d_in[6];
    const int*   edge_rels    = (const int*)  d_in[7];
    float*       out          = (float*)d_out;

    fused_kernel<<<NBLK, THREADS>>>(emb, all_emb, tail_r, source_idx,
                                    relation_ids, heads, tails, edge_rels, out);
}

// round 12
// speedup vs baseline: 2.0619x; 2.0619x over previous
#include <cuda_runtime.h>
#include <math.h>

// Problem constants (fixed shapes from the reference)
#define N_ENT   14541
#define N_REL   237
#define M_EDGES 272115
#define D       256
#define BS      16
#define NT      4                       // entities per tile
#define HB      8                       // batch items per warp (half of BS)
#define OUT_ELEMS (N_ENT * BS)

#define TILES   (((N_ENT + NT - 1) / NT) * 2)   // 7272 warp-tiles (x2 for b-split)
#define DBLK    ((TILES + 7) / 8)               // 909 dist blocks (8 warps each)

// Scratch (static device arrays; no runtime allocation)
__device__ float    g_sig[N_ENT * BS];
__device__ unsigned g_relmask[N_REL];

// ---------------------------------------------------------------------------
// dist: sig[n][b] = sigmoid(12 - sum_d |rel[b,d]| * |emb[b,d] - all_emb[n,d]|)
//       with sig[source_idx[b]][b] = 0 (sigmoid(12-1e8) == 0 in fp32).
// One warp = 4 entities x 8 batch items (warp-tile t: n0=(t>>1)*4, b0=(t&1)*8).
// Adjacent warps share all_emb rows -> L1 reuse. 32 accs + cap 128 regs
// => 2 blocks/SM resident (16 warps/SM).
// Side jobs: zero `out`; block 0 builds the relation->batch bitmask.
// ---------------------------------------------------------------------------
__global__ void __launch_bounds__(256, 2) dist_kernel(
    const float* __restrict__ emb,
    const float* __restrict__ all_emb,
    const float* __restrict__ tail_r,
    const int*   __restrict__ source_idx,
    const int*   __restrict__ relation_ids,
    float*       __restrict__ out)
{
    __shared__ float es[BS * D];   // emb[b][d]
    __shared__ float rs[BS * D];   // |tail_r[relation_ids[b]][d]|
    __shared__ int   s_src[BS];

    const int tid  = threadIdx.x;
    const int lane = tid & 31;

    // Zero the output buffer (1 float/thread over 909*256 threads).
    {
        const int g = blockIdx.x * 256 + tid;
        if (g < OUT_ELEMS) out[g] = 0.f;
    }

    // Block 0: relation->batch bitmask for the edge kernel.
    if (blockIdx.x == 0 && tid < N_REL) {
        unsigned m = 0;
        #pragma unroll
        for (int b = 0; b < BS; b++)
            m |= (relation_ids[b] == tid) ? (1u << b) : 0u;
        g_relmask[tid] = m;
    }

    if (tid < BS) s_src[tid] = source_idx[tid];
    for (int i = tid; i < BS * D; i += 256) {
        int b = i >> 8;          // i / D
        int d = i & (D - 1);     // i % D
        es[i] = emb[i];
        rs[i] = fabsf(tail_r[relation_ids[b] * D + d]);
    }
    __syncthreads();

    const int t = blockIdx.x * 8 + (tid >> 5);   // warp-tile id
    if (t >= TILES) return;
    const int n0 = (t >> 1) * NT;                // entity base
    const int b0 = (t & 1) * HB;                 // batch half base

    // Preload all_emb rows (coalesced LDG.128; pair-warp hits L1).
    float4 xl[NT], xh[NT];
    #pragma unroll
    for (int n = 0; n < NT; n++) {
        int nn = n0 + n; if (nn >= N_ENT) nn = N_ENT - 1;
        const float4* row = (const float4*)(all_emb + nn * D);
        xl[n] = row[lane];
        xh[n] = row[32 + lane];
    }

    float acc[NT * HB];
    #pragma unroll
    for (int i = 0; i < NT * HB; i++) acc[i] = 0.f;

    const float4* es4 = (const float4*)es;
    const float4* rs4 = (const float4*)rs;

    #pragma unroll
    for (int bi = 0; bi < HB; bi++) {
        const int b = b0 + bi;
        float4 e0 = es4[b * 64 + lane];
        float4 e1 = es4[b * 64 + 32 + lane];
        float4 r0 = rs4[b * 64 + lane];
        float4 r1 = rs4[b * 64 + 32 + lane];
        #pragma unroll
        for (int n = 0; n < NT; n++) {
            float s = acc[n * HB + bi];
            s += r0.x * fabsf(e0.x - xl[n].x);
            s += r0.y * fabsf(e0.y - xl[n].y);
            s += r0.z * fabsf(e0.z - xl[n].z);
            s += r0.w * fabsf(e0.w - xl[n].w);
            s += r1.x * fabsf(e1.x - xh[n].x);
            s += r1.y * fabsf(e1.y - xh[n].y);
            s += r1.z * fabsf(e1.z - xh[n].z);
            s += r1.w * fabsf(e1.w - xh[n].w);
            acc[n * HB + bi] = s;
        }
    }

    // Value-splitting butterfly: 32 partials -> 31 shuffles; lane L ends
    // with flat sum L, where flat = n_local*8 + bi.
    #pragma unroll
    for (int step = 0; step < 5; step++) {
        const int mask = 16 >> step;
        const int V    = 32 >> step;
        const bool hi  = (lane & mask) != 0;
        #pragma unroll
        for (int i = 0; i < V / 2; i++) {
            float send = hi ? acc[i]         : acc[i + V / 2];
            float keep = hi ? acc[i + V / 2] : acc[i];
            float other = __shfl_xor_sync(0xffffffffu, send, mask);
            acc[i] = keep + other;
        }
    }

    // Epilogue: mask + sigmoid, 32B-segment stores (4 segments/warp).
    const int nn = n0 + (lane >> 3);
    const int b  = b0 + (lane & 7);
    if (nn < N_ENT) {
        float s0 = 1.0f / (1.0f + __expf(acc[0] - 12.0f));
        if (nn == s_src[b]) s0 = 0.0f;
        g_sig[nn * BS + b] = s0;
    }
}

// ---------------------------------------------------------------------------
// edge: one edge per thread. Coalesced rel load -> L1-resident bitmask probe;
// ~93% of threads exit immediately. Survivors gather sig[head][b] and
// atomically scatter-add onto out[b][tail].
// ---------------------------------------------------------------------------
__global__ void __launch_bounds__(256, 8) edge_kernel(
    const int* __restrict__ heads,
    const int* __restrict__ tails,
    const int* __restrict__ rels,
    float*     __restrict__ out)
{
    const int i = blockIdx.x * 256 + threadIdx.x;
    if (i >= M_EDGES) return;

    const int r = __ldg(rels + i);
    unsigned m = g_relmask[r];
    if (!m) return;

    const int h = __ldg(heads + i);
    const int t = __ldg(tails + i);
    do {
        int b = __ffs(m) - 1;
        m &= m - 1;
        atomicAdd(out + b * N_ENT + t, g_sig[h * BS + b]);
    } while (m);
}

// ---------------------------------------------------------------------------
extern "C" void kernel_launch(void* const* d_in, const int* in_sizes, int n_in,
                              void* d_out, int out_size) {
    const float* emb          = (const float*)d_in[0];
    const float* all_emb      = (const float*)d_in[1];
    const float* tail_r       = (const float*)d_in[2];
    const int*   source_idx   = (const int*)  d_in[3];
    const int*   relation_ids = (const int*)  d_in[4];
    const int*   heads        = (const int*)  d_in[5];
    const int*   tails        = (const int*)  d_in[6];
    const int*   edge_rels    = (const int*)  d_in[7];
    float*       out          = (float*)d_out;

    dist_kernel<<<DBLK, 256>>>(emb, all_emb, tail_r, source_idx,
                               relation_ids, out);

    const int eblocks = (M_EDGES + 255) / 256;     // 1063
    edge_kernel<<<eblocks, 256>>>(heads, tails, edge_rels, out);
}